// round 11
// baseline (speedup 1.0000x reference)
#include <cuda_runtime.h>
#include <cstdint>

// Problem constants (fixed by the reference setup_inputs)
#define TOKENS   4096
#define IN_F     8192
#define OUT_F    8192
#define NGROUPS  (IN_F / 64)      // 128 scale groups per output row
#define OCHUNKS  256              // o-reduction split
#define O_PER_CHUNK (OUT_F / OCHUNKS)  // 32
#define TILE_I   2048             // columns per k1 block (2 x 1024 halves)
#define RSTAGE   8                // stage-A outputs per strip
#define NSTRIP   2                // i-dimension pipeline strips
#define STRIP_W  (IN_F / NSTRIP)  // 4096 columns per strip

// Scratch (allocation-free rule: __device__ globals)
__device__ float g_partial[OCHUNKS * IN_F];   // 8 MB partial v sums
__device__ float g_stage[RSTAGE * IN_F];      // 256 KB stage-A sums
__device__ float g_v[IN_F];                   // final v vector
__device__ float g_y[NSTRIP * TOKENS];        // per-strip xv partials

__constant__ float c_nf4[16] = {
    -1.0f, -0.6961928009986877f, -0.5250730514526367f, -0.39491748809814453f,
    -0.28444138169288635f, -0.18477343022823334f, -0.09105003625154495f, 0.0f,
    0.07958029955625534f, 0.16093020141124725f, 0.24611230194568634f,
    0.33791524171829224f, 0.44070982933044434f, 0.5626170039176941f,
    0.7229568362236023f, 1.0f
};

// ---------------------------------------------------------------------------
// Kernel 1 (round-7 measured-best inner config), restricted to one i-strip.
// partial[oc][i] = sum_{o in chunk oc} NF4[codes[o,i]]*scales[o,i/64]*w2[o]
// Per-strip grid: (STRIP_W/TILE_I, OCHUNKS) = (2, 256) = 512 blocks.
// ---------------------------------------------------------------------------
__global__ void __launch_bounds__(256) k_dequant_reduce(
    const int*   __restrict__ codes,   // [OUT_F, IN_F]
    const float* __restrict__ scales,  // [OUT_F, NGROUPS]
    const float* __restrict__ w2,      // [OUT_F]
    const int strip)
{
    __shared__ float tbl[16 * 32];                // lane-replicated NF4 table
    __shared__ float s_tab[O_PER_CHUNK * 32];     // w2*scale, 32x32 = 4 KB

    const int tid = threadIdx.x;
    for (int idx = tid; idx < 16 * 32; idx += 256)
        tbl[idx] = c_nf4[idx >> 5];

    const int oc    = blockIdx.y;
    const int o0    = oc * O_PER_CHUNK;
    const int ibase = strip * STRIP_W + blockIdx.x * TILE_I;
    const int gbase = ibase / 64;                 // 32 groups per tile

#pragma unroll
    for (int k = 0; k < 4; ++k) {
        int idx = tid + k * 256;
        int o = idx >> 5;            // 0..31
        int g = idx & 31;            // 0..31
        s_tab[idx] = __ldg(&w2[o0 + o]) *
                     __ldg(&scales[(size_t)(o0 + o) * NGROUPS + gbase + g]);
    }
    __syncthreads();

    const int lane = tid & 31;
    const float* lt = &tbl[lane];                 // lt[c<<5]: own-bank hit

    const int i0 = ibase + tid * 4;
    const int i1 = i0 + 1024;
    const int g0 = tid >> 4;                      // 0..15
    const int g1 = g0 + 16;                       // 16..31

    const int4* p0 = reinterpret_cast<const int4*>(codes) +
                     (((size_t)o0 * IN_F + i0) >> 2);
    const int4* p1 = p0 + (1024 >> 2);
    const size_t cstride = IN_F / 4;

    float a0 = 0.f, a1 = 0.f, a2 = 0.f, a3 = 0.f;
    float b0 = 0.f, b1 = 0.f, b2 = 0.f, b3 = 0.f;

#pragma unroll 8
    for (int o = 0; o < O_PER_CHUNK; ++o) {
        int4 ca = __ldcs(p0);                     // streaming, one-touch
        int4 cb = __ldcs(p1);
        p0 += cstride;
        p1 += cstride;
        float sa = s_tab[o * 32 + g0];            // broadcast LDS
        float sb = s_tab[o * 32 + g1];
        a0 += sa * lt[ca.x << 5];
        a1 += sa * lt[ca.y << 5];
        a2 += sa * lt[ca.z << 5];
        a3 += sa * lt[ca.w << 5];
        b0 += sb * lt[cb.x << 5];
        b1 += sb * lt[cb.y << 5];
        b2 += sb * lt[cb.z << 5];
        b3 += sb * lt[cb.w << 5];
    }

    float* dst = &g_partial[(size_t)oc * IN_F];
    *reinterpret_cast<float4*>(&dst[i0]) = make_float4(a0, a1, a2, a3);
    *reinterpret_cast<float4*>(&dst[i1]) = make_float4(b0, b1, b2, b3);
}

// ---------------------------------------------------------------------------
// Reduce stage A (per strip): g_stage[cj][i] = sum of 32 chunks.
// Grid (STRIP_W/256, RSTAGE) = (16, 8) = 128 blocks.
// ---------------------------------------------------------------------------
__global__ void __launch_bounds__(256) k_reduce_a(const int strip)
{
    const int i  = strip * STRIP_W + blockIdx.x * 256 + threadIdx.x;
    const int c0 = blockIdx.y * (OCHUNKS / RSTAGE);
    float s = 0.f;
#pragma unroll
    for (int c = 0; c < OCHUNKS / RSTAGE; ++c)
        s += g_partial[(size_t)(c0 + c) * IN_F + i];
    g_stage[(size_t)blockIdx.y * IN_F + i] = s;
}

// ---------------------------------------------------------------------------
// Reduce stage B (per strip): v[i] = sum of 8 stage values (fixed order).
// Grid: STRIP_W/256 = 16 blocks.
// ---------------------------------------------------------------------------
__global__ void __launch_bounds__(256) k_reduce_b(const int strip)
{
    const int i = strip * STRIP_W + blockIdx.x * 256 + threadIdx.x;
    float s = 0.f;
#pragma unroll
    for (int c = 0; c < RSTAGE; ++c)
        s += g_stage[(size_t)c * IN_F + i];
    g_v[i] = s;
}

// ---------------------------------------------------------------------------
// Kernel 2 (per strip): g_y[strip][t] = dot(x[t, strip cols], v[strip cols]).
// 1 token per block (<=32 regs -> 8 blocks/SM, ~100% occ), 4096 blocks.
// ---------------------------------------------------------------------------
__global__ void __launch_bounds__(256) k_xv_strip(
    const float* __restrict__ x,      // [TOKENS, IN_F]
    const int strip)
{
    const int t   = blockIdx.x;
    const int tid = threadIdx.x;
    const int cbase = strip * (STRIP_W / 4);      // float4 index base

    const float4* xr = reinterpret_cast<const float4*>(x + (size_t)t * IN_F) + cbase;
    const float4* vr = reinterpret_cast<const float4*>(g_v) + cbase;

    float sum = 0.f;
#pragma unroll
    for (int k = 0; k < (STRIP_W / 4) / 256; ++k) {   // 4 iterations
        int j = tid + k * 256;
        float4 a = __ldcs(&xr[j]);                // streamed, one-touch
        float4 b = __ldg(&vr[j]);                 // hot in L2/L1
        sum += a.x * b.x + a.y * b.y + a.z * b.z + a.w * b.w;
    }

    for (int off = 16; off > 0; off >>= 1)
        sum += __shfl_down_sync(0xFFFFFFFFu, sum, off);

    __shared__ float ws[8];
    const int wid  = tid >> 5;
    const int lane = tid & 31;
    if (lane == 0) ws[wid] = sum;
    __syncthreads();

    if (wid == 0) {
        float v = (lane < 8) ? ws[lane] : 0.f;
        for (int off = 4; off > 0; off >>= 1)
            v += __shfl_down_sync(0xFFFFFFFFu, v, off);
        if (lane == 0) g_y[strip * TOKENS + t] = v;
    }
}

// ---------------------------------------------------------------------------
// Combine: out[t] = sum over strips of g_y[s][t]  (fixed order).
// ---------------------------------------------------------------------------
__global__ void __launch_bounds__(256) k_combine(float* __restrict__ out)
{
    const int t = blockIdx.x * 256 + threadIdx.x;
    float s = 0.f;
#pragma unroll
    for (int c = 0; c < NSTRIP; ++c)
        s += g_y[c * TOKENS + t];
    out[t] = s;
}

// ---------------------------------------------------------------------------
// Launch: 2-strip pipeline across two streams (capture-fork pattern).
//   main:  k1(s0) -e0->  k1(s1) -e1->                      wait(aux) combine
//   aux :        wait(e0) redA(0) redB(0) xv(0)  wait(e1) redA(1) ... xv(1)
// aux strip-s work overlaps k1 strip-(s+1) on the main stream.
// ---------------------------------------------------------------------------
static cudaStream_t s_aux = nullptr;
static cudaEvent_t  ev_k1[NSTRIP];
static cudaEvent_t  ev_aux = nullptr;

extern "C" void kernel_launch(void* const* d_in, const int* in_sizes, int n_in,
                              void* d_out, int out_size)
{
    const float* x      = (const float*)d_in[0];   // [4096, 8192] f32
    const int*   codes  = (const int*)  d_in[1];   // [8192, 8192] i32 (0..15)
    const float* scales = (const float*)d_in[2];   // [8192, 128]  f32
    const float* w2     = (const float*)d_in[3];   // [1, 8192]    f32
    float*       out    = (float*)d_out;           // [4096, 1]    f32

    (void)in_sizes; (void)n_in; (void)out_size;

    if (s_aux == nullptr) {                        // one-time handle creation
        cudaStreamCreateWithFlags(&s_aux, cudaStreamNonBlocking);
        for (int s = 0; s < NSTRIP; ++s)
            cudaEventCreateWithFlags(&ev_k1[s], cudaEventDisableTiming);
        cudaEventCreateWithFlags(&ev_aux, cudaEventDisableTiming);
    }

    dim3 g1(STRIP_W / TILE_I, OCHUNKS);            // (2, 256) per strip
    dim3 gr(STRIP_W / 256, RSTAGE);                // (16, 8) per strip

    // Main stream: the two k1 strips back-to-back, each signaling an event.
    for (int s = 0; s < NSTRIP; ++s) {
        k_dequant_reduce<<<g1, 256>>>(codes, scales, w2, s);
        cudaEventRecord(ev_k1[s], 0);
    }

    // Aux stream: per-strip reduce + xv, gated on that strip's k1 event.
    for (int s = 0; s < NSTRIP; ++s) {
        cudaStreamWaitEvent(s_aux, ev_k1[s], 0);
        k_reduce_a<<<gr, 256, 0, s_aux>>>(s);
        k_reduce_b<<<STRIP_W / 256, 256, 0, s_aux>>>(s);
        k_xv_strip<<<TOKENS, 256, 0, s_aux>>>(x, s);
    }
    cudaEventRecord(ev_aux, s_aux);

    // Join and combine on the main stream.
    cudaStreamWaitEvent(0, ev_aux, 0);
    k_combine<<<TOKENS / 256, 256>>>(out);
}